// round 13
// baseline (speedup 1.0000x reference)
#include <cuda_runtime.h>
#include <math.h>

#define D_  5
#define B_  2048
#define L_  50
#define DH_ 128
#define QK_ 64

// ---------------- device scratch (no allocation allowed) ----------------
__device__ float g_loss[B_];
__device__ float g_gb[B_ * 256];          // gamma|beta per b
__device__ float g_stats[2 * D_ * DH_];   // mean [0..639], rstd [640..1279]
__device__ float g_WkiT[QK_ * DH_];
__device__ float g_WksT[QK_ * DH_];

// ---------------- smem layout (float offsets) ----------------
#define S_HI   0        // 5*50*128 = 32000
#define S_HS   32000    // 50*128   = 6400
#define S_U    38400    // 128
#define S_C    38528    // 5*128
#define S_Q    39168    // 5*64
#define S_QK   39488    // 5*128
#define S_QS   40128    // 5*128
#define S_AI   40768    // 5*64 (scores -> attention, stride 64, 50 used)
#define S_AS   41088    // 5*64
#define S_HBI  41408    // 5*128
#define S_HBS  42048    // 5*128
#define S_HIQ  42688    // 5*64  h_i
#define S_HSQ  43008    // 5*64  h_s
#define S_PART 43328    // 2*4*320 = 2560
#define S_DOT  45888    // 32
#define S_MISC 45920    // 16 (qbias_i[5], qbias_s[5])
#define S_Z    45936    // 64
#define SMEM_FLOATS 46000
#define SMEM_BYTES (SMEM_FLOATS * 4)

// ---------------- K0: transpose Wki / Wks for coalesced reads ----------------
__global__ void cdi_pre(const float* __restrict__ Wki, const float* __restrict__ Wks) {
    int i = blockIdx.x * 256 + threadIdx.x;       // i = dh*64 + q
    if (i < DH_ * QK_) {
        int dh = i >> 6, q = i & 63;
        g_WkiT[q * DH_ + dh] = Wki[i];
        g_WksT[q * DH_ + dh] = Wks[i];
    }
}

// ---------------- K1: per-b fused attention + loss + gb ----------------
__global__ void __launch_bounds__(256, 1) cdi_main(
    const float* __restrict__ u, const float* __restrict__ Hintra,
    const float* __restrict__ Hshare,
    const int*   __restrict__ dom,
    const float* __restrict__ Wq,  const float* __restrict__ bq,
    const float* __restrict__ bki,
    const float* __restrict__ Wvi, const float* __restrict__ bvi,
    const float* __restrict__ bks,
    const float* __restrict__ Wvs, const float* __restrict__ bvs,
    const float* __restrict__ Wf,  const float* __restrict__ bf,
    const float* __restrict__ Wgb, const float* __restrict__ bgb)
{
    extern __shared__ float sm[];
    const int b    = blockIdx.x;
    const int tid  = threadIdx.x;
    const int warp = tid >> 5, lane = tid & 31;

    // ---- load H_intra[*, b], H_share[b], u[b] into smem (H read once) ----
    {
        float4* dst = (float4*)(sm + S_HI);
        for (int i = tid; i < 8000; i += 256) {
            int d = i / 1600, j = i - d * 1600;
            dst[i] = __ldg((const float4*)Hintra + (size_t)(d * B_ + b) * 1600 + j);
        }
        const float4* hsrc = (const float4*)Hshare + (size_t)b * 1600;
        float4* hdst = (float4*)(sm + S_HS);
        for (int i = tid; i < 1600; i += 256) hdst[i] = __ldg(hsrc + i);
        if (tid < 32) ((float4*)(sm + S_U))[tid] = __ldg((const float4*)u + b * 32 + tid);
    }
    __syncthreads();

    // ---- c[d] = mean over L ----
    for (int i = tid; i < 640; i += 256) {
        int d = i >> 7, dh = i & 127;
        const float* p = sm + S_HI + d * 6400 + dh;
        float s = 0.f;
        #pragma unroll
        for (int l = 0; l < L_; l++) s += p[l * 128];
        sm[S_C + i] = s * (1.f / 50.f);
    }
    __syncthreads();

    // ---- Q[d] = [u;c_d] @ Wq + bq  (k-split: 4 groups of 64, Wq read once) ----
    {
        int g = tid >> 6, q = tid & 63;
        if (g < 2) {  // u part (shared across d)
            float a = 0.f;
            int k0 = g * 64;
            #pragma unroll 8
            for (int k = k0; k < k0 + 64; k++) a += sm[S_U + k] * __ldg(Wq + k * 64 + q);
            #pragma unroll
            for (int d = 0; d < 5; d++) sm[S_PART + g * 320 + d * 64 + q] = a;
        } else {      // c part
            float acc[5] = {0.f, 0.f, 0.f, 0.f, 0.f};
            int k0 = g * 64;
            #pragma unroll 4
            for (int k = k0; k < k0 + 64; k++) {
                float w = __ldg(Wq + k * 64 + q);
                int kc = k - 128;
                #pragma unroll
                for (int d = 0; d < 5; d++) acc[d] += sm[S_C + d * 128 + kc] * w;
            }
            #pragma unroll
            for (int d = 0; d < 5; d++) sm[S_PART + g * 320 + d * 64 + q] = acc[d];
        }
    }
    __syncthreads();
    for (int i = tid; i < 320; i += 256) {
        float s = __ldg(bq + (i & 63));
        #pragma unroll
        for (int g = 0; g < 4; g++) s += sm[S_PART + g * 320 + i];
        sm[S_Q + i] = s;
    }
    __syncthreads();

    // ---- qk_vec = Wki @ Q, qs_vec = Wks @ Q ; qbias = Q·bki / Q·bks ----
    for (int i = tid; i < 640; i += 256) {
        int d = i >> 7, dh = i & 127;
        const float* qp = sm + S_Q + d * 64;
        float si = 0.f, ss = 0.f;
        #pragma unroll 8
        for (int q = 0; q < 64; q++) {
            float qv = qp[q];
            si += g_WkiT[q * 128 + dh] * qv;
            ss += g_WksT[q * 128 + dh] * qv;
        }
        sm[S_QK + i] = si;
        sm[S_QS + i] = ss;
    }
    if (tid < 10) {
        int d = (tid < 5) ? tid : tid - 5;
        const float* bb = (tid < 5) ? bki : bks;
        const float* qp = sm + S_Q + d * 64;
        float s = 0.f;
        #pragma unroll 8
        for (int q = 0; q < 64; q++) s += qp[q] * __ldg(bb + q);
        sm[S_MISC + tid] = s;
    }
    __syncthreads();

    // ---- scores: 250 intra + 250 share dot products (warp per task) ----
    for (int t = warp; t < 500; t += 8) {
        int path = (t >= 250);
        int tt = path ? t - 250 : t;
        int d = tt / 50, l = tt - d * 50;
        const float* hp = path ? (sm + S_HS + l * 128) : (sm + S_HI + d * 6400 + l * 128);
        const float* qv = path ? (sm + S_QS + d * 128) : (sm + S_QK + d * 128);
        float s = hp[lane]      * qv[lane]
                + hp[lane + 32] * qv[lane + 32]
                + hp[lane + 64] * qv[lane + 64]
                + hp[lane + 96] * qv[lane + 96];
        #pragma unroll
        for (int o = 16; o; o >>= 1) s += __shfl_xor_sync(0xffffffffu, s, o);
        if (lane == 0) {
            float bias = sm[S_MISC + (path ? 5 + d : d)];
            sm[(path ? S_AS : S_AI) + d * 64 + l] = (s + bias) * 0.125f;  // /sqrt(64)
        }
    }
    __syncthreads();

    // ---- softmax over L (10 rows, warp per row) ----
    for (int t = warp; t < 10; t += 8) {
        float* row = sm + ((t < 5) ? (S_AI + t * 64) : (S_AS + (t - 5) * 64));
        float v0 = (lane < 50)      ? row[lane]      : -1e30f;
        float v1 = (lane + 32 < 50) ? row[lane + 32] : -1e30f;
        float m = fmaxf(v0, v1);
        #pragma unroll
        for (int o = 16; o; o >>= 1) m = fmaxf(m, __shfl_xor_sync(0xffffffffu, m, o));
        float e0 = (lane < 50)      ? __expf(v0 - m) : 0.f;
        float e1 = (lane + 32 < 50) ? __expf(v1 - m) : 0.f;
        float s = e0 + e1;
        #pragma unroll
        for (int o = 16; o; o >>= 1) s += __shfl_xor_sync(0xffffffffu, s, o);
        float inv = 1.f / s;
        if (lane < 50)      row[lane]      = e0 * inv;
        if (lane + 32 < 50) row[lane + 32] = e1 * inv;
    }
    __syncthreads();

    // ---- hbar = a @ H (attention-weighted sums, both paths) ----
    for (int i = tid; i < 640; i += 256) {
        int d = i >> 7, dh = i & 127;
        const float* hp  = sm + S_HI + d * 6400 + dh;
        const float* ap  = sm + S_AI + d * 64;
        const float* hps = sm + S_HS + dh;
        const float* aps = sm + S_AS + d * 64;
        float s1 = 0.f, s2 = 0.f;
        #pragma unroll
        for (int l = 0; l < L_; l++) {
            s1 += ap[l]  * hp[l * 128];
            s2 += aps[l] * hps[l * 128];
        }
        sm[S_HBI + i] = s1;
        sm[S_HBS + i] = s2;
    }
    __syncthreads();

    // ---- h_i = hbar_i @ Wvi + bvi ; h_s = hbar_s @ Wvs + bvs (k-split) ----
    {
        int g = tid >> 6, q = tid & 63;
        float ai[5] = {0.f, 0.f, 0.f, 0.f, 0.f};
        float as_[5] = {0.f, 0.f, 0.f, 0.f, 0.f};
        int dh0 = g * 32;
        for (int dh = dh0; dh < dh0 + 32; dh++) {
            float wi = __ldg(Wvi + dh * 64 + q);
            float ws = __ldg(Wvs + dh * 64 + q);
            #pragma unroll
            for (int d = 0; d < 5; d++) {
                ai[d]  += sm[S_HBI + d * 128 + dh] * wi;
                as_[d] += sm[S_HBS + d * 128 + dh] * ws;
            }
        }
        #pragma unroll
        for (int d = 0; d < 5; d++) {
            sm[S_PART + g * 320 + d * 64 + q]        = ai[d];
            sm[S_PART + 1280 + g * 320 + d * 64 + q] = as_[d];
        }
    }
    __syncthreads();
    for (int i = tid; i < 320; i += 256) {
        int q = i & 63;
        float s1 = __ldg(bvi + q), s2 = __ldg(bvs + q);
        #pragma unroll
        for (int g = 0; g < 4; g++) {
            s1 += sm[S_PART + g * 320 + i];
            s2 += sm[S_PART + 1280 + g * 320 + i];
        }
        sm[S_HIQ + i] = s1;
        sm[S_HSQ + i] = s2;
    }
    __syncthreads();

    // ---- contrastive dots: dii (15 upper-tri), dis (5), dss (5) ----
    for (int t = warp; t < 25; t += 8) {
        const float *x, *y;
        if (t < 15) {
            int d = 0, tt = t;
            while (tt >= 5 - d) { tt -= 5 - d; d++; }
            int e = d + tt;
            x = sm + S_HIQ + d * 64; y = sm + S_HIQ + e * 64;
        } else if (t < 20) {
            x = sm + S_HIQ + (t - 15) * 64; y = sm + S_HSQ + (t - 15) * 64;
        } else {
            x = sm + S_HSQ + (t - 20) * 64; y = x;
        }
        float v = x[lane] * y[lane] + x[lane + 32] * y[lane + 32];
        #pragma unroll
        for (int o = 16; o; o >>= 1) v += __shfl_xor_sync(0xffffffffu, v, o);
        if (lane == 0) sm[S_DOT + t] = v;
    }
    __syncthreads();

    const int d0 = __ldg(dom + b);

    // ---- z_sel = [h_i[d0]; h_s[d0]] @ Wf + bf  (threads 0..63) ----
    if (tid < 64) {
        const float* hi0 = sm + S_HIQ + d0 * 64;
        const float* hs0 = sm + S_HSQ + d0 * 64;
        float s = __ldg(bf + tid);
        #pragma unroll 8
        for (int k = 0; k < 64; k++) s += hi0[k] * __ldg(Wf + k * 64 + tid);
        #pragma unroll 8
        for (int k = 0; k < 64; k++) s += hs0[k] * __ldg(Wf + (64 + k) * 64 + tid);
        sm[S_Z + tid] = s;
    }

    // ---- contrastive loss for this b (single thread, distinct warp) ----
    if (tid == 255) {
        float dii[5][5], dis[5], dss[5];
        int idx = 0;
        #pragma unroll
        for (int d = 0; d < 5; d++)
            #pragma unroll
            for (int e = d; e < 5; e++) {
                float v = sm[S_DOT + idx]; idx++;
                dii[d][e] = v; dii[e][d] = v;
            }
        #pragma unroll
        for (int d = 0; d < 5; d++) { dis[d] = sm[S_DOT + 15 + d]; dss[d] = sm[S_DOT + 20 + d]; }
        float inv_n[5];
        #pragma unroll
        for (int d = 0; d < 5; d++) inv_n[d] = 1.f / fmaxf(sqrtf(dii[d][d]), 1e-12f);
        float loss = 0.f;
        #pragma unroll
        for (int d = 0; d < 5; d++) {
            float invs = 1.f / fmaxf(sqrtf(dss[d]), 1e-12f);
            float pos  = dis[d] * inv_n[d] * invs;
            float denom = 0.f;
            #pragma unroll
            for (int e = 0; e < 5; e++) denom += expf(dii[d][e] * inv_n[d] * inv_n[e]);
            loss -= logf(expf(pos) / (denom + 1e-8f) + 1e-8f);
        }
        g_loss[b] = loss;
    }
    __syncthreads();

    // ---- gb = z @ Wgb + bgb  (256 outputs = gamma|beta) ----
    {
        float s = __ldg(bgb + tid);
        const float* zp = sm + S_Z;
        #pragma unroll 8
        for (int k = 0; k < 64; k++) s += zp[k] * __ldg(Wgb + k * 256 + tid);
        g_gb[b * 256 + tid] = s;
    }
}

// ---------------- K2: per-domain segment mean / rstd (deterministic) ----------------
__global__ void cdi_stats(const float* __restrict__ h, const int* __restrict__ dom) {
    int d = blockIdx.x;        // 5 blocks
    int dh = threadIdx.x;      // 128 threads
    float s = 0.f, s2 = 0.f, cnt = 0.f;
    #pragma unroll 4
    for (int b = 0; b < B_; b++) {
        if (__ldg(dom + b) == d) {
            float v = __ldg(h + b * 128 + dh);
            s += v; s2 += v * v; cnt += 1.f;
        }
    }
    float c = fmaxf(cnt, 1.f);
    float mean = s / c;
    float var = s2 / c - mean * mean;
    g_stats[d * 128 + dh]       = mean;
    g_stats[640 + d * 128 + dh] = rsqrtf(var + 1e-5f);
}

// ---------------- K3: AdaNorm finalize ----------------
__global__ void cdi_final(const float* __restrict__ h, const int* __restrict__ dom,
                          float* __restrict__ out) {
    int i = blockIdx.x * blockDim.x + threadIdx.x;
    if (i < B_ * DH_) {
        int b = i >> 7, dh = i & 127;
        int d = __ldg(dom + b);
        float hv = __ldg(h + i);
        float hn = (hv - g_stats[d * 128 + dh]) * g_stats[640 + d * 128 + dh];
        out[i] = g_gb[b * 256 + dh] * hn + g_gb[b * 256 + 128 + dh] + hv;
    }
}

// ---------------- K4: deterministic loss reduction ----------------
__global__ void cdi_loss(float* __restrict__ out, int out_size) {
    __shared__ float red[256];
    int tid = threadIdx.x;
    float s = 0.f;
    for (int b = tid; b < B_; b += 256) s += g_loss[b];
    red[tid] = s;
    __syncthreads();
    for (int o = 128; o > 0; o >>= 1) {
        if (tid < o) red[tid] += red[tid + o];
        __syncthreads();
    }
    if (tid == 0) out[out_size - 1] = red[0] * (1.f / (float)(B_ * D_));
}

// ---------------- launch ----------------
extern "C" void kernel_launch(void* const* d_in, const int* in_sizes, int n_in,
                              void* d_out, int out_size) {
    const float* u      = (const float*)d_in[0];
    const float* Hintra = (const float*)d_in[1];
    const float* Hshare = (const float*)d_in[2];
    const float* h      = (const float*)d_in[3];
    const int*   dom    = (const int*)d_in[4];
    const float* Wq  = (const float*)d_in[5];  const float* bq  = (const float*)d_in[6];
    const float* Wki = (const float*)d_in[7];  const float* bki = (const float*)d_in[8];
    const float* Wvi = (const float*)d_in[9];  const float* bvi = (const float*)d_in[10];
    const float* Wks = (const float*)d_in[11]; const float* bks = (const float*)d_in[12];
    const float* Wvs = (const float*)d_in[13]; const float* bvs = (const float*)d_in[14];
    const float* Wf  = (const float*)d_in[15]; const float* bf  = (const float*)d_in[16];
    const float* Wgb = (const float*)d_in[17]; const float* bgb = (const float*)d_in[18];
    float* out = (float*)d_out;

    cudaFuncSetAttribute(cdi_main, cudaFuncAttributeMaxDynamicSharedMemorySize, SMEM_BYTES);

    cdi_pre<<<32, 256>>>(Wki, Wks);
    cdi_main<<<B_, 256, SMEM_BYTES>>>(u, Hintra, Hshare, dom,
                                      Wq, bq, bki, Wvi, bvi, bks, Wvs, bvs,
                                      Wf, bf, Wgb, bgb);
    cdi_stats<<<D_, DH_>>>(h, dom);
    cdi_final<<<(B_ * DH_ + 255) / 256, 256>>>(h, dom, out);
    cdi_loss<<<1, 256>>>(out, out_size);
}

// round 14
// speedup vs baseline: 1.0030x; 1.0030x over previous
#include <cuda_runtime.h>
#include <math.h>

#define D_  5
#define B_  2048
#define L_  50
#define DH_ 128
#define QK_ 64

// ---------------- device scratch (no allocation allowed) ----------------
__device__ float g_loss[B_];
__device__ float g_gb[B_ * 256];          // gamma|beta per b
__device__ float g_stats[2 * D_ * DH_];   // mean [0..639], rstd [640..1279]
__device__ float g_WkiT[QK_ * DH_];
__device__ float g_WksT[QK_ * DH_];

// ---------------- smem layout (float offsets) ----------------
#define S_HI   0        // 5*50*128 = 32000
#define S_HS   32000    // 50*128   = 6400
#define S_U    38400    // 128
#define S_C    38528    // 5*128
#define S_Q    39168    // 5*64
#define S_QK   39488    // 5*128
#define S_QS   40128    // 5*128
#define S_AI   40768    // 5*64 (scores -> attention, stride 64, 50 used)
#define S_AS   41088    // 5*64
#define S_HBI  41408    // 5*128
#define S_HBS  42048    // 5*128
#define S_HIQ  42688    // 5*64  h_i
#define S_HSQ  43008    // 5*64  h_s
#define S_PART 43328    // 2*4*320 = 2560
#define S_DOT  45888    // 32
#define S_MISC 45920    // 16 (qbias_i[5], qbias_s[5])
#define S_Z    45936    // 64
#define SMEM_FLOATS 46000
#define SMEM_BYTES (SMEM_FLOATS * 4)

// ---------------- K0: transpose Wki / Wks for coalesced reads ----------------
__global__ void cdi_pre(const float* __restrict__ Wki, const float* __restrict__ Wks) {
    int i = blockIdx.x * 256 + threadIdx.x;       // i = dh*64 + q
    if (i < DH_ * QK_) {
        int dh = i >> 6, q = i & 63;
        g_WkiT[q * DH_ + dh] = Wki[i];
        g_WksT[q * DH_ + dh] = Wks[i];
    }
}

// ---------------- K1: per-b fused attention + loss + gb ----------------
__global__ void __launch_bounds__(256, 1) cdi_main(
    const float* __restrict__ u, const float* __restrict__ Hintra,
    const float* __restrict__ Hshare,
    const int*   __restrict__ dom,
    const float* __restrict__ Wq,  const float* __restrict__ bq,
    const float* __restrict__ bki,
    const float* __restrict__ Wvi, const float* __restrict__ bvi,
    const float* __restrict__ bks,
    const float* __restrict__ Wvs, const float* __restrict__ bvs,
    const float* __restrict__ Wf,  const float* __restrict__ bf,
    const float* __restrict__ Wgb, const float* __restrict__ bgb)
{
    extern __shared__ float sm[];
    const int b    = blockIdx.x;
    const int tid  = threadIdx.x;
    const int warp = tid >> 5, lane = tid & 31;

    // ---- load H_intra[*, b], H_share[b], u[b] into smem (H read once) ----
    {
        float4* dst = (float4*)(sm + S_HI);
        for (int i = tid; i < 8000; i += 256) {
            int d = i / 1600, j = i - d * 1600;
            dst[i] = __ldg((const float4*)Hintra + (size_t)(d * B_ + b) * 1600 + j);
        }
        const float4* hsrc = (const float4*)Hshare + (size_t)b * 1600;
        float4* hdst = (float4*)(sm + S_HS);
        for (int i = tid; i < 1600; i += 256) hdst[i] = __ldg(hsrc + i);
        if (tid < 32) ((float4*)(sm + S_U))[tid] = __ldg((const float4*)u + b * 32 + tid);
    }
    __syncthreads();

    // ---- c[d] = mean over L ----
    for (int i = tid; i < 640; i += 256) {
        int d = i >> 7, dh = i & 127;
        const float* p = sm + S_HI + d * 6400 + dh;
        float s = 0.f;
        #pragma unroll
        for (int l = 0; l < L_; l++) s += p[l * 128];
        sm[S_C + i] = s * (1.f / 50.f);
    }
    __syncthreads();

    // ---- Q[d] = [u;c_d] @ Wq + bq  (k-split: 4 groups of 64, Wq read once) ----
    {
        int g = tid >> 6, q = tid & 63;
        if (g < 2) {  // u part (shared across d)
            float a = 0.f;
            int k0 = g * 64;
            #pragma unroll 8
            for (int k = k0; k < k0 + 64; k++) a += sm[S_U + k] * __ldg(Wq + k * 64 + q);
            #pragma unroll
            for (int d = 0; d < 5; d++) sm[S_PART + g * 320 + d * 64 + q] = a;
        } else {      // c part
            float acc[5] = {0.f, 0.f, 0.f, 0.f, 0.f};
            int k0 = g * 64;
            #pragma unroll 4
            for (int k = k0; k < k0 + 64; k++) {
                float w = __ldg(Wq + k * 64 + q);
                int kc = k - 128;
                #pragma unroll
                for (int d = 0; d < 5; d++) acc[d] += sm[S_C + d * 128 + kc] * w;
            }
            #pragma unroll
            for (int d = 0; d < 5; d++) sm[S_PART + g * 320 + d * 64 + q] = acc[d];
        }
    }
    __syncthreads();
    for (int i = tid; i < 320; i += 256) {
        float s = __ldg(bq + (i & 63));
        #pragma unroll
        for (int g = 0; g < 4; g++) s += sm[S_PART + g * 320 + i];
        sm[S_Q + i] = s;
    }
    __syncthreads();

    // ---- qk_vec = Wki @ Q, qs_vec = Wks @ Q ; qbias = Q·bki / Q·bks ----
    for (int i = tid; i < 640; i += 256) {
        int d = i >> 7, dh = i & 127;
        const float* qp = sm + S_Q + d * 64;
        float si = 0.f, ss = 0.f;
        #pragma unroll 8
        for (int q = 0; q < 64; q++) {
            float qv = qp[q];
            si += g_WkiT[q * 128 + dh] * qv;
            ss += g_WksT[q * 128 + dh] * qv;
        }
        sm[S_QK + i] = si;
        sm[S_QS + i] = ss;
    }
    if (tid < 10) {
        int d = (tid < 5) ? tid : tid - 5;
        const float* bb = (tid < 5) ? bki : bks;
        const float* qp = sm + S_Q + d * 64;
        float s = 0.f;
        #pragma unroll 8
        for (int q = 0; q < 64; q++) s += qp[q] * __ldg(bb + q);
        sm[S_MISC + tid] = s;
    }
    __syncthreads();

    // ---- scores: 250 intra + 250 share dot products (warp per task) ----
    for (int t = warp; t < 500; t += 8) {
        int path = (t >= 250);
        int tt = path ? t - 250 : t;
        int d = tt / 50, l = tt - d * 50;
        const float* hp = path ? (sm + S_HS + l * 128) : (sm + S_HI + d * 6400 + l * 128);
        const float* qv = path ? (sm + S_QS + d * 128) : (sm + S_QK + d * 128);
        float s = hp[lane]      * qv[lane]
                + hp[lane + 32] * qv[lane + 32]
                + hp[lane + 64] * qv[lane + 64]
                + hp[lane + 96] * qv[lane + 96];
        #pragma unroll
        for (int o = 16; o; o >>= 1) s += __shfl_xor_sync(0xffffffffu, s, o);
        if (lane == 0) {
            float bias = sm[S_MISC + (path ? 5 + d : d)];
            sm[(path ? S_AS : S_AI) + d * 64 + l] = (s + bias) * 0.125f;  // /sqrt(64)
        }
    }
    __syncthreads();

    // ---- softmax over L (10 rows, warp per row) ----
    for (int t = warp; t < 10; t += 8) {
        float* row = sm + ((t < 5) ? (S_AI + t * 64) : (S_AS + (t - 5) * 64));
        float v0 = (lane < 50)      ? row[lane]      : -1e30f;
        float v1 = (lane + 32 < 50) ? row[lane + 32] : -1e30f;
        float m = fmaxf(v0, v1);
        #pragma unroll
        for (int o = 16; o; o >>= 1) m = fmaxf(m, __shfl_xor_sync(0xffffffffu, m, o));
        float e0 = (lane < 50)      ? __expf(v0 - m) : 0.f;
        float e1 = (lane + 32 < 50) ? __expf(v1 - m) : 0.f;
        float s = e0 + e1;
        #pragma unroll
        for (int o = 16; o; o >>= 1) s += __shfl_xor_sync(0xffffffffu, s, o);
        float inv = 1.f / s;
        if (lane < 50)      row[lane]      = e0 * inv;
        if (lane + 32 < 50) row[lane + 32] = e1 * inv;
    }
    __syncthreads();

    // ---- hbar = a @ H (attention-weighted sums, both paths) ----
    for (int i = tid; i < 640; i += 256) {
        int d = i >> 7, dh = i & 127;
        const float* hp  = sm + S_HI + d * 6400 + dh;
        const float* ap  = sm + S_AI + d * 64;
        const float* hps = sm + S_HS + dh;
        const float* aps = sm + S_AS + d * 64;
        float s1 = 0.f, s2 = 0.f;
        #pragma unroll
        for (int l = 0; l < L_; l++) {
            s1 += ap[l]  * hp[l * 128];
            s2 += aps[l] * hps[l * 128];
        }
        sm[S_HBI + i] = s1;
        sm[S_HBS + i] = s2;
    }
    __syncthreads();

    // ---- h_i = hbar_i @ Wvi + bvi ; h_s = hbar_s @ Wvs + bvs (k-split) ----
    {
        int g = tid >> 6, q = tid & 63;
        float ai[5] = {0.f, 0.f, 0.f, 0.f, 0.f};
        float as_[5] = {0.f, 0.f, 0.f, 0.f, 0.f};
        int dh0 = g * 32;
        for (int dh = dh0; dh < dh0 + 32; dh++) {
            float wi = __ldg(Wvi + dh * 64 + q);
            float ws = __ldg(Wvs + dh * 64 + q);
            #pragma unroll
            for (int d = 0; d < 5; d++) {
                ai[d]  += sm[S_HBI + d * 128 + dh] * wi;
                as_[d] += sm[S_HBS + d * 128 + dh] * ws;
            }
        }
        #pragma unroll
        for (int d = 0; d < 5; d++) {
            sm[S_PART + g * 320 + d * 64 + q]        = ai[d];
            sm[S_PART + 1280 + g * 320 + d * 64 + q] = as_[d];
        }
    }
    __syncthreads();
    for (int i = tid; i < 320; i += 256) {
        int q = i & 63;
        float s1 = __ldg(bvi + q), s2 = __ldg(bvs + q);
        #pragma unroll
        for (int g = 0; g < 4; g++) {
            s1 += sm[S_PART + g * 320 + i];
            s2 += sm[S_PART + 1280 + g * 320 + i];
        }
        sm[S_HIQ + i] = s1;
        sm[S_HSQ + i] = s2;
    }
    __syncthreads();

    // ---- contrastive dots: dii (15 upper-tri), dis (5), dss (5) ----
    for (int t = warp; t < 25; t += 8) {
        const float *x, *y;
        if (t < 15) {
            int d = 0, tt = t;
            while (tt >= 5 - d) { tt -= 5 - d; d++; }
            int e = d + tt;
            x = sm + S_HIQ + d * 64; y = sm + S_HIQ + e * 64;
        } else if (t < 20) {
            x = sm + S_HIQ + (t - 15) * 64; y = sm + S_HSQ + (t - 15) * 64;
        } else {
            x = sm + S_HSQ + (t - 20) * 64; y = x;
        }
        float v = x[lane] * y[lane] + x[lane + 32] * y[lane + 32];
        #pragma unroll
        for (int o = 16; o; o >>= 1) v += __shfl_xor_sync(0xffffffffu, v, o);
        if (lane == 0) sm[S_DOT + t] = v;
    }
    __syncthreads();

    const int d0 = __ldg(dom + b);

    // ---- z_sel = [h_i[d0]; h_s[d0]] @ Wf + bf  (threads 0..63) ----
    if (tid < 64) {
        const float* hi0 = sm + S_HIQ + d0 * 64;
        const float* hs0 = sm + S_HSQ + d0 * 64;
        float s = __ldg(bf + tid);
        #pragma unroll 8
        for (int k = 0; k < 64; k++) s += hi0[k] * __ldg(Wf + k * 64 + tid);
        #pragma unroll 8
        for (int k = 0; k < 64; k++) s += hs0[k] * __ldg(Wf + (64 + k) * 64 + tid);
        sm[S_Z + tid] = s;
    }

    // ---- contrastive loss for this b (single thread, distinct warp) ----
    if (tid == 255) {
        float dii[5][5], dis[5], dss[5];
        int idx = 0;
        #pragma unroll
        for (int d = 0; d < 5; d++)
            #pragma unroll
            for (int e = d; e < 5; e++) {
                float v = sm[S_DOT + idx]; idx++;
                dii[d][e] = v; dii[e][d] = v;
            }
        #pragma unroll
        for (int d = 0; d < 5; d++) { dis[d] = sm[S_DOT + 15 + d]; dss[d] = sm[S_DOT + 20 + d]; }
        float inv_n[5];
        #pragma unroll
        for (int d = 0; d < 5; d++) inv_n[d] = 1.f / fmaxf(sqrtf(dii[d][d]), 1e-12f);
        float loss = 0.f;
        #pragma unroll
        for (int d = 0; d < 5; d++) {
            float invs = 1.f / fmaxf(sqrtf(dss[d]), 1e-12f);
            float pos  = dis[d] * inv_n[d] * invs;
            float denom = 0.f;
            #pragma unroll
            for (int e = 0; e < 5; e++) denom += expf(dii[d][e] * inv_n[d] * inv_n[e]);
            loss -= logf(expf(pos) / (denom + 1e-8f) + 1e-8f);
        }
        g_loss[b] = loss;
    }
    __syncthreads();

    // ---- gb = z @ Wgb + bgb  (256 outputs = gamma|beta) ----
    {
        float s = __ldg(bgb + tid);
        const float* zp = sm + S_Z;
        #pragma unroll 8
        for (int k = 0; k < 64; k++) s += zp[k] * __ldg(Wgb + k * 256 + tid);
        g_gb[b * 256 + tid] = s;
    }
}

// ---------------- K2: per-domain segment mean / rstd (deterministic) ----------------
__global__ void cdi_stats(const float* __restrict__ h, const int* __restrict__ dom) {
    int d = blockIdx.x;        // 5 blocks
    int dh = threadIdx.x;      // 128 threads
    float s = 0.f, s2 = 0.f, cnt = 0.f;
    #pragma unroll 4
    for (int b = 0; b < B_; b++) {
        if (__ldg(dom + b) == d) {
            float v = __ldg(h + b * 128 + dh);
            s += v; s2 += v * v; cnt += 1.f;
        }
    }
    float c = fmaxf(cnt, 1.f);
    float mean = s / c;
    float var = s2 / c - mean * mean;
    g_stats[d * 128 + dh]       = mean;
    g_stats[640 + d * 128 + dh] = rsqrtf(var + 1e-5f);
}

// ---------------- K3: AdaNorm finalize ----------------
__global__ void cdi_final(const float* __restrict__ h, const int* __restrict__ dom,
                          float* __restrict__ out) {
    int i = blockIdx.x * blockDim.x + threadIdx.x;
    if (i < B_ * DH_) {
        int b = i >> 7, dh = i & 127;
        int d = __ldg(dom + b);
        float hv = __ldg(h + i);
        float hn = (hv - g_stats[d * 128 + dh]) * g_stats[640 + d * 128 + dh];
        out[i] = g_gb[b * 256 + dh] * hn + g_gb[b * 256 + 128 + dh] + hv;
    }
}

// ---------------- K4: deterministic loss reduction ----------------
__global__ void cdi_loss(float* __restrict__ out, int out_size) {
    __shared__ float red[256];
    int tid = threadIdx.x;
    float s = 0.f;
    for (int b = tid; b < B_; b += 256) s += g_loss[b];
    red[tid] = s;
    __syncthreads();
    for (int o = 128; o > 0; o >>= 1) {
        if (tid < o) red[tid] += red[tid + o];
        __syncthreads();
    }
    if (tid == 0) out[out_size - 1] = red[0] * (1.f / (float)(B_ * D_));
}

// ---------------- launch ----------------
extern "C" void kernel_launch(void* const* d_in, const int* in_sizes, int n_in,
                              void* d_out, int out_size) {
    const float* u      = (const float*)d_in[0];
    const float* Hintra = (const float*)d_in[1];
    const float* Hshare = (const float*)d_in[2];
    const float* h      = (const float*)d_in[3];
    const int*   dom    = (const int*)d_in[4];
    const float* Wq  = (const float*)d_in[5];  const float* bq  = (const float*)d_in[6];
    const float* Wki = (const float*)d_in[7];  const float* bki = (const float*)d_in[8];
    const float* Wvi = (const float*)d_in[9];  const float* bvi = (const float*)d_in[10];
    const float* Wks = (const float*)d_in[11]; const float* bks = (const float*)d_in[12];
    const float* Wvs = (const float*)d_in[13]; const float* bvs = (const float*)d_in[14];
    const float* Wf  = (const float*)d_in[15]; const float* bf  = (const float*)d_in[16];
    const float* Wgb = (const float*)d_in[17]; const float* bgb = (const float*)d_in[18];
    float* out = (float*)d_out;

    cudaFuncSetAttribute(cdi_main, cudaFuncAttributeMaxDynamicSharedMemorySize, SMEM_BYTES);

    cdi_pre<<<32, 256>>>(Wki, Wks);
    cdi_main<<<B_, 256, SMEM_BYTES>>>(u, Hintra, Hshare, dom,
                                      Wq, bq, bki, Wvi, bvi, bks, Wvs, bvs,
                                      Wf, bf, Wgb, bgb);
    cdi_stats<<<D_, DH_>>>(h, dom);
    cdi_final<<<(B_ * DH_ + 255) / 256, 256>>>(h, dom, out);
    cdi_loss<<<1, 256>>>(out, out_size);
}

// round 15
// speedup vs baseline: 1.0057x; 1.0027x over previous
#include <cuda_runtime.h>
#include <math.h>

#define D_  5
#define B_  2048
#define L_  50
#define DH_ 128
#define QK_ 64

// ---------------- device scratch (no allocation allowed) ----------------
__device__ float g_loss[B_];
__device__ float g_gb[B_ * 256];          // gamma|beta per b
__device__ float g_stats[2 * D_ * DH_];   // mean [0..639], rstd [640..1279]
__device__ float g_WkiT[QK_ * DH_];
__device__ float g_WksT[QK_ * DH_];

// ---------------- smem layout (float offsets) ----------------
#define S_HI   0        // 5*50*128 = 32000
#define S_HS   32000    // 50*128   = 6400
#define S_U    38400    // 128
#define S_C    38528    // 5*128
#define S_Q    39168    // 5*64
#define S_QK   39488    // 5*128
#define S_QS   40128    // 5*128
#define S_AI   40768    // 5*64 (scores -> attention, stride 64, 50 used)
#define S_AS   41088    // 5*64
#define S_HBI  41408    // 5*128
#define S_HBS  42048    // 5*128
#define S_HIQ  42688    // 5*64  h_i
#define S_HSQ  43008    // 5*64  h_s
#define S_PART 43328    // 2*4*320 = 2560
#define S_DOT  45888    // 32
#define S_MISC 45920    // 16 (qbias_i[5], qbias_s[5])
#define S_Z    45936    // 64
#define SMEM_FLOATS 46000
#define SMEM_BYTES (SMEM_FLOATS * 4)

// ---------------- K0: transpose Wki / Wks for coalesced reads ----------------
__global__ void cdi_pre(const float* __restrict__ Wki, const float* __restrict__ Wks) {
    int i = blockIdx.x * 256 + threadIdx.x;       // i = dh*64 + q
    if (i < DH_ * QK_) {
        int dh = i >> 6, q = i & 63;
        g_WkiT[q * DH_ + dh] = Wki[i];
        g_WksT[q * DH_ + dh] = Wks[i];
    }
}

// ---------------- K1: per-b fused attention + loss + gb ----------------
__global__ void __launch_bounds__(256, 1) cdi_main(
    const float* __restrict__ u, const float* __restrict__ Hintra,
    const float* __restrict__ Hshare,
    const int*   __restrict__ dom,
    const float* __restrict__ Wq,  const float* __restrict__ bq,
    const float* __restrict__ bki,
    const float* __restrict__ Wvi, const float* __restrict__ bvi,
    const float* __restrict__ bks,
    const float* __restrict__ Wvs, const float* __restrict__ bvs,
    const float* __restrict__ Wf,  const float* __restrict__ bf,
    const float* __restrict__ Wgb, const float* __restrict__ bgb)
{
    extern __shared__ float sm[];
    const int b    = blockIdx.x;
    const int tid  = threadIdx.x;
    const int warp = tid >> 5, lane = tid & 31;

    // ---- load H_intra[*, b], H_share[b], u[b] into smem (H read once) ----
    {
        float4* dst = (float4*)(sm + S_HI);
        for (int i = tid; i < 8000; i += 256) {
            int d = i / 1600, j = i - d * 1600;
            dst[i] = __ldg((const float4*)Hintra + (size_t)(d * B_ + b) * 1600 + j);
        }
        const float4* hsrc = (const float4*)Hshare + (size_t)b * 1600;
        float4* hdst = (float4*)(sm + S_HS);
        for (int i = tid; i < 1600; i += 256) hdst[i] = __ldg(hsrc + i);
        if (tid < 32) ((float4*)(sm + S_U))[tid] = __ldg((const float4*)u + b * 32 + tid);
    }
    __syncthreads();

    // ---- c[d] = mean over L ----
    for (int i = tid; i < 640; i += 256) {
        int d = i >> 7, dh = i & 127;
        const float* p = sm + S_HI + d * 6400 + dh;
        float s = 0.f;
        #pragma unroll
        for (int l = 0; l < L_; l++) s += p[l * 128];
        sm[S_C + i] = s * (1.f / 50.f);
    }
    __syncthreads();

    // ---- Q[d] = [u;c_d] @ Wq + bq  (k-split: 4 groups of 64, Wq read once) ----
    {
        int g = tid >> 6, q = tid & 63;
        if (g < 2) {  // u part (shared across d)
            float a = 0.f;
            int k0 = g * 64;
            #pragma unroll 8
            for (int k = k0; k < k0 + 64; k++) a += sm[S_U + k] * __ldg(Wq + k * 64 + q);
            #pragma unroll
            for (int d = 0; d < 5; d++) sm[S_PART + g * 320 + d * 64 + q] = a;
        } else {      // c part
            float acc[5] = {0.f, 0.f, 0.f, 0.f, 0.f};
            int k0 = g * 64;
            #pragma unroll 4
            for (int k = k0; k < k0 + 64; k++) {
                float w = __ldg(Wq + k * 64 + q);
                int kc = k - 128;
                #pragma unroll
                for (int d = 0; d < 5; d++) acc[d] += sm[S_C + d * 128 + kc] * w;
            }
            #pragma unroll
            for (int d = 0; d < 5; d++) sm[S_PART + g * 320 + d * 64 + q] = acc[d];
        }
    }
    __syncthreads();
    for (int i = tid; i < 320; i += 256) {
        float s = __ldg(bq + (i & 63));
        #pragma unroll
        for (int g = 0; g < 4; g++) s += sm[S_PART + g * 320 + i];
        sm[S_Q + i] = s;
    }
    __syncthreads();

    // ---- qk_vec = Wki @ Q, qs_vec = Wks @ Q ; qbias = Q·bki / Q·bks ----
    for (int i = tid; i < 640; i += 256) {
        int d = i >> 7, dh = i & 127;
        const float* qp = sm + S_Q + d * 64;
        float si = 0.f, ss = 0.f;
        #pragma unroll 8
        for (int q = 0; q < 64; q++) {
            float qv = qp[q];
            si += g_WkiT[q * 128 + dh] * qv;
            ss += g_WksT[q * 128 + dh] * qv;
        }
        sm[S_QK + i] = si;
        sm[S_QS + i] = ss;
    }
    if (tid < 10) {
        int d = (tid < 5) ? tid : tid - 5;
        const float* bb = (tid < 5) ? bki : bks;
        const float* qp = sm + S_Q + d * 64;
        float s = 0.f;
        #pragma unroll 8
        for (int q = 0; q < 64; q++) s += qp[q] * __ldg(bb + q);
        sm[S_MISC + tid] = s;
    }
    __syncthreads();

    // ---- scores: 250 intra + 250 share dot products (warp per task) ----
    for (int t = warp; t < 500; t += 8) {
        int path = (t >= 250);
        int tt = path ? t - 250 : t;
        int d = tt / 50, l = tt - d * 50;
        const float* hp = path ? (sm + S_HS + l * 128) : (sm + S_HI + d * 6400 + l * 128);
        const float* qv = path ? (sm + S_QS + d * 128) : (sm + S_QK + d * 128);
        float s = hp[lane]      * qv[lane]
                + hp[lane + 32] * qv[lane + 32]
                + hp[lane + 64] * qv[lane + 64]
                + hp[lane + 96] * qv[lane + 96];
        #pragma unroll
        for (int o = 16; o; o >>= 1) s += __shfl_xor_sync(0xffffffffu, s, o);
        if (lane == 0) {
            float bias = sm[S_MISC + (path ? 5 + d : d)];
            sm[(path ? S_AS : S_AI) + d * 64 + l] = (s + bias) * 0.125f;  // /sqrt(64)
        }
    }
    __syncthreads();

    // ---- softmax over L (10 rows, warp per row) ----
    for (int t = warp; t < 10; t += 8) {
        float* row = sm + ((t < 5) ? (S_AI + t * 64) : (S_AS + (t - 5) * 64));
        float v0 = (lane < 50)      ? row[lane]      : -1e30f;
        float v1 = (lane + 32 < 50) ? row[lane + 32] : -1e30f;
        float m = fmaxf(v0, v1);
        #pragma unroll
        for (int o = 16; o; o >>= 1) m = fmaxf(m, __shfl_xor_sync(0xffffffffu, m, o));
        float e0 = (lane < 50)      ? __expf(v0 - m) : 0.f;
        float e1 = (lane + 32 < 50) ? __expf(v1 - m) : 0.f;
        float s = e0 + e1;
        #pragma unroll
        for (int o = 16; o; o >>= 1) s += __shfl_xor_sync(0xffffffffu, s, o);
        float inv = 1.f / s;
        if (lane < 50)      row[lane]      = e0 * inv;
        if (lane + 32 < 50) row[lane + 32] = e1 * inv;
    }
    __syncthreads();

    // ---- hbar = a @ H (attention-weighted sums, both paths) ----
    for (int i = tid; i < 640; i += 256) {
        int d = i >> 7, dh = i & 127;
        const float* hp  = sm + S_HI + d * 6400 + dh;
        const float* ap  = sm + S_AI + d * 64;
        const float* hps = sm + S_HS + dh;
        const float* aps = sm + S_AS + d * 64;
        float s1 = 0.f, s2 = 0.f;
        #pragma unroll
        for (int l = 0; l < L_; l++) {
            s1 += ap[l]  * hp[l * 128];
            s2 += aps[l] * hps[l * 128];
        }
        sm[S_HBI + i] = s1;
        sm[S_HBS + i] = s2;
    }
    __syncthreads();

    // ---- h_i = hbar_i @ Wvi + bvi ; h_s = hbar_s @ Wvs + bvs (k-split) ----
    {
        int g = tid >> 6, q = tid & 63;
        float ai[5] = {0.f, 0.f, 0.f, 0.f, 0.f};
        float as_[5] = {0.f, 0.f, 0.f, 0.f, 0.f};
        int dh0 = g * 32;
        for (int dh = dh0; dh < dh0 + 32; dh++) {
            float wi = __ldg(Wvi + dh * 64 + q);
            float ws = __ldg(Wvs + dh * 64 + q);
            #pragma unroll
            for (int d = 0; d < 5; d++) {
                ai[d]  += sm[S_HBI + d * 128 + dh] * wi;
                as_[d] += sm[S_HBS + d * 128 + dh] * ws;
            }
        }
        #pragma unroll
        for (int d = 0; d < 5; d++) {
            sm[S_PART + g * 320 + d * 64 + q]        = ai[d];
            sm[S_PART + 1280 + g * 320 + d * 64 + q] = as_[d];
        }
    }
    __syncthreads();
    for (int i = tid; i < 320; i += 256) {
        int q = i & 63;
        float s1 = __ldg(bvi + q), s2 = __ldg(bvs + q);
        #pragma unroll
        for (int g = 0; g < 4; g++) {
            s1 += sm[S_PART + g * 320 + i];
            s2 += sm[S_PART + 1280 + g * 320 + i];
        }
        sm[S_HIQ + i] = s1;
        sm[S_HSQ + i] = s2;
    }
    __syncthreads();

    // ---- contrastive dots: dii (15 upper-tri), dis (5), dss (5) ----
    for (int t = warp; t < 25; t += 8) {
        const float *x, *y;
        if (t < 15) {
            int d = 0, tt = t;
            while (tt >= 5 - d) { tt -= 5 - d; d++; }
            int e = d + tt;
            x = sm + S_HIQ + d * 64; y = sm + S_HIQ + e * 64;
        } else if (t < 20) {
            x = sm + S_HIQ + (t - 15) * 64; y = sm + S_HSQ + (t - 15) * 64;
        } else {
            x = sm + S_HSQ + (t - 20) * 64; y = x;
        }
        float v = x[lane] * y[lane] + x[lane + 32] * y[lane + 32];
        #pragma unroll
        for (int o = 16; o; o >>= 1) v += __shfl_xor_sync(0xffffffffu, v, o);
        if (lane == 0) sm[S_DOT + t] = v;
    }
    __syncthreads();

    const int d0 = __ldg(dom + b);

    // ---- z_sel = [h_i[d0]; h_s[d0]] @ Wf + bf  (threads 0..63) ----
    if (tid < 64) {
        const float* hi0 = sm + S_HIQ + d0 * 64;
        const float* hs0 = sm + S_HSQ + d0 * 64;
        float s = __ldg(bf + tid);
        #pragma unroll 8
        for (int k = 0; k < 64; k++) s += hi0[k] * __ldg(Wf + k * 64 + tid);
        #pragma unroll 8
        for (int k = 0; k < 64; k++) s += hs0[k] * __ldg(Wf + (64 + k) * 64 + tid);
        sm[S_Z + tid] = s;
    }

    // ---- contrastive loss for this b (single thread, distinct warp) ----
    if (tid == 255) {
        float dii[5][5], dis[5], dss[5];
        int idx = 0;
        #pragma unroll
        for (int d = 0; d < 5; d++)
            #pragma unroll
            for (int e = d; e < 5; e++) {
                float v = sm[S_DOT + idx]; idx++;
                dii[d][e] = v; dii[e][d] = v;
            }
        #pragma unroll
        for (int d = 0; d < 5; d++) { dis[d] = sm[S_DOT + 15 + d]; dss[d] = sm[S_DOT + 20 + d]; }
        float inv_n[5];
        #pragma unroll
        for (int d = 0; d < 5; d++) inv_n[d] = 1.f / fmaxf(sqrtf(dii[d][d]), 1e-12f);
        float loss = 0.f;
        #pragma unroll
        for (int d = 0; d < 5; d++) {
            float invs = 1.f / fmaxf(sqrtf(dss[d]), 1e-12f);
            float pos  = dis[d] * inv_n[d] * invs;
            float denom = 0.f;
            #pragma unroll
            for (int e = 0; e < 5; e++) denom += expf(dii[d][e] * inv_n[d] * inv_n[e]);
            loss -= logf(expf(pos) / (denom + 1e-8f) + 1e-8f);
        }
        g_loss[b] = loss;
    }
    __syncthreads();

    // ---- gb = z @ Wgb + bgb  (256 outputs = gamma|beta) ----
    {
        float s = __ldg(bgb + tid);
        const float* zp = sm + S_Z;
        #pragma unroll 8
        for (int k = 0; k < 64; k++) s += zp[k] * __ldg(Wgb + k * 256 + tid);
        g_gb[b * 256 + tid] = s;
    }
}

// ---------------- K2: per-domain segment mean / rstd (deterministic) ----------------
__global__ void cdi_stats(const float* __restrict__ h, const int* __restrict__ dom) {
    int d = blockIdx.x;        // 5 blocks
    int dh = threadIdx.x;      // 128 threads
    float s = 0.f, s2 = 0.f, cnt = 0.f;
    #pragma unroll 4
    for (int b = 0; b < B_; b++) {
        if (__ldg(dom + b) == d) {
            float v = __ldg(h + b * 128 + dh);
            s += v; s2 += v * v; cnt += 1.f;
        }
    }
    float c = fmaxf(cnt, 1.f);
    float mean = s / c;
    float var = s2 / c - mean * mean;
    g_stats[d * 128 + dh]       = mean;
    g_stats[640 + d * 128 + dh] = rsqrtf(var + 1e-5f);
}

// ---------------- K3: AdaNorm finalize ----------------
__global__ void cdi_final(const float* __restrict__ h, const int* __restrict__ dom,
                          float* __restrict__ out) {
    int i = blockIdx.x * blockDim.x + threadIdx.x;
    if (i < B_ * DH_) {
        int b = i >> 7, dh = i & 127;
        int d = __ldg(dom + b);
        float hv = __ldg(h + i);
        float hn = (hv - g_stats[d * 128 + dh]) * g_stats[640 + d * 128 + dh];
        out[i] = g_gb[b * 256 + dh] * hn + g_gb[b * 256 + 128 + dh] + hv;
    }
}

// ---------------- K4: deterministic loss reduction ----------------
__global__ void cdi_loss(float* __restrict__ out, int out_size) {
    __shared__ float red[256];
    int tid = threadIdx.x;
    float s = 0.f;
    for (int b = tid; b < B_; b += 256) s += g_loss[b];
    red[tid] = s;
    __syncthreads();
    for (int o = 128; o > 0; o >>= 1) {
        if (tid < o) red[tid] += red[tid + o];
        __syncthreads();
    }
    if (tid == 0) out[out_size - 1] = red[0] * (1.f / (float)(B_ * D_));
}

// ---------------- launch ----------------
extern "C" void kernel_launch(void* const* d_in, const int* in_sizes, int n_in,
                              void* d_out, int out_size) {
    const float* u      = (const float*)d_in[0];
    const float* Hintra = (const float*)d_in[1];
    const float* Hshare = (const float*)d_in[2];
    const float* h      = (const float*)d_in[3];
    const int*   dom    = (const int*)d_in[4];
    const float* Wq  = (const float*)d_in[5];  const float* bq  = (const float*)d_in[6];
    const float* Wki = (const float*)d_in[7];  const float* bki = (const float*)d_in[8];
    const float* Wvi = (const float*)d_in[9];  const float* bvi = (const float*)d_in[10];
    const float* Wks = (const float*)d_in[11]; const float* bks = (const float*)d_in[12];
    const float* Wvs = (const float*)d_in[13]; const float* bvs = (const float*)d_in[14];
    const float* Wf  = (const float*)d_in[15]; const float* bf  = (const float*)d_in[16];
    const float* Wgb = (const float*)d_in[17]; const float* bgb = (const float*)d_in[18];
    float* out = (float*)d_out;

    cudaFuncSetAttribute(cdi_main, cudaFuncAttributeMaxDynamicSharedMemorySize, SMEM_BYTES);

    cdi_pre<<<32, 256>>>(Wki, Wks);
    cdi_main<<<B_, 256, SMEM_BYTES>>>(u, Hintra, Hshare, dom,
                                      Wq, bq, bki, Wvi, bvi, bks, Wvs, bvs,
                                      Wf, bf, Wgb, bgb);
    cdi_stats<<<D_, DH_>>>(h, dom);
    cdi_final<<<(B_ * DH_ + 255) / 256, 256>>>(h, dom, out);
    cdi_loss<<<1, 256>>>(out, out_size);
}